// round 9
// baseline (speedup 1.0000x reference)
#include <cuda_runtime.h>
#include <math.h>

#define BB 4
#define LL 1024
#define DD 768
#define DD2 1536
#define HH 12
#define HEADD 64
#define HIDD 3072
#define NITER 12
#define ALPHA_C 0.1f
#define LN_EPS_C 1e-5f

#define ND ((long)BB * LL * DD)          /* 3,145,728 */
#define ND2 ((long)BB * LL * DD2)        /* 6,291,456 */
#define NH ((long)BB * LL * HIDD)        /* 12,582,912 */
#define NATT ((long)BB * HH * LL * LL)   /* 50,331,648 */

// ---------------- scratch (__device__ globals; no allocs allowed) ----------
__device__ float g_g[ND];        // layernorm output
__device__ float g_qk[ND2];      // [B*L, 1536]: cols 0:768 = q, 768:1536 = k
__device__ float g_d[ND2];       // [B*L, 1536]: cols 0:768 = P@K, 768:1536 = P^T@Q
__device__ float g_wc[DD2 * DD]; // combined [Wq; Wk]  (1536 x 768)
__device__ float g_hp[NH];       // relu(beta_hop * g @ W_hop)
__device__ float g_att[NATT];    // attention logits -> probabilities in place

// ---------------- reductions ----------------------------------------------
__device__ __forceinline__ float warpRedSum(float v) {
#pragma unroll
    for (int o = 16; o > 0; o >>= 1) v += __shfl_xor_sync(0xffffffffu, v, o);
    return v;
}
__device__ __forceinline__ float warpRedMax(float v) {
#pragma unroll
    for (int o = 16; o > 0; o >>= 1) v = fmaxf(v, __shfl_xor_sync(0xffffffffu, v, o));
    return v;
}
template <int NT>
__device__ __forceinline__ float blockRedSum(float v) {
    __shared__ float sh[NT / 32];
    int lane = threadIdx.x & 31, w = threadIdx.x >> 5;
    v = warpRedSum(v);
    if (lane == 0) sh[w] = v;
    __syncthreads();
    if (w == 0) {
        float t = (lane < NT / 32) ? sh[lane] : 0.0f;
        t = warpRedSum(t);
        if (lane == 0) sh[0] = t;
    }
    __syncthreads();
    float r = sh[0];
    __syncthreads();
    return r;
}
template <int NT>
__device__ __forceinline__ float blockRedMax(float v) {
    __shared__ float sh[NT / 32];
    int lane = threadIdx.x & 31, w = threadIdx.x >> 5;
    v = warpRedMax(v);
    if (lane == 0) sh[w] = v;
    __syncthreads();
    if (w == 0) {
        float t = (lane < NT / 32) ? sh[lane] : -INFINITY;
        t = warpRedMax(t);
        if (lane == 0) sh[0] = t;
    }
    __syncthreads();
    float r = sh[0];
    __syncthreads();
    return r;
}

// =============== 128x128x16 SGEMM, 8x8 microtile, double-buffered ==========
// A is always [M,K] row-major.
//   TB=false: B is [K,N] row-major.  TB=true: B is [N,K] row-major.
// EPI==1: v = relu(s*acc); C = v; e_ptr[m0/LL] += -0.5*sum v^2 (block-reduced)
// Batched via grid.z: offset = (z/inner)*s?1 + (z%inner)*s?2
template <bool TB, int EPI>
__global__ __launch_bounds__(256) void gemm128(
    const float* __restrict__ A, const float* __restrict__ Bm, float* __restrict__ C,
    int M, int N, int K, int lda, int ldb, int ldc,
    long sA1, long sA2, long sB1, long sB2, long sC1, long sC2, int inner,
    const float* __restrict__ scale_ptr, float cscale, int accum,
    float* __restrict__ e_ptr)
{
    __shared__ float As[2][16][132];
    __shared__ float Bs[2][16][132];
    int bz = blockIdx.z;
    int bo = bz / inner, bi = bz % inner;
    A  += bo * sA1 + bi * sA2;
    Bm += bo * sB1 + bi * sB2;
    C  += bo * sC1 + bi * sC2;
    int m0 = blockIdx.y * 128, n0 = blockIdx.x * 128;
    int tid = threadIdx.x;
    int tx = tid & 15, ty = tid >> 4;          // microtile coords (n, m)
    int br = tid >> 5, bc = tid & 31;          // B-load coords (TB=false)

    float acc[8][8];
#pragma unroll
    for (int i = 0; i < 8; i++)
#pragma unroll
        for (int j = 0; j < 8; j++) acc[i][j] = 0.0f;

    float ra[8];              // A staging: 8 scalars (transposed store)
    float rb[8];              // B staging TB=true: 8 scalars
    float4 vb0, vb1;          // B staging TB=false: 2 float4

#define LOAD_REGS(k0)                                                          \
    do {                                                                       \
        _Pragma("unroll")                                                      \
        for (int r = 0; r < 8; r++)                                            \
            ra[r] = A[(long)(m0 + ty + 16 * r) * lda + ((k0) + tx)];           \
        if (!TB) {                                                             \
            vb0 = *(const float4*)(Bm + (long)((k0) + br) * ldb + n0 + bc * 4);\
            vb1 = *(const float4*)(Bm + (long)((k0) + br + 8) * ldb + n0 + bc * 4);\
        } else {                                                               \
            _Pragma("unroll")                                                  \
            for (int r = 0; r < 8; r++)                                        \
                rb[r] = Bm[(long)(n0 + ty + 16 * r) * ldb + ((k0) + tx)];      \
        }                                                                      \
    } while (0)

#define STORE_SMEM(b)                                                          \
    do {                                                                       \
        _Pragma("unroll")                                                      \
        for (int r = 0; r < 8; r++) As[b][tx][ty + 16 * r] = ra[r];            \
        if (!TB) {                                                             \
            *(float4*)&Bs[b][br][bc * 4] = vb0;                                \
            *(float4*)&Bs[b][br + 8][bc * 4] = vb1;                            \
        } else {                                                               \
            _Pragma("unroll")                                                  \
            for (int r = 0; r < 8; r++) Bs[b][tx][ty + 16 * r] = rb[r];        \
        }                                                                      \
    } while (0)

#define COMPUTE(b)                                                             \
    do {                                                                       \
        _Pragma("unroll")                                                      \
        for (int kk = 0; kk < 16; kk++) {                                      \
            float4 a0 = *(const float4*)&As[b][kk][ty * 8];                    \
            float4 a1 = *(const float4*)&As[b][kk][ty * 8 + 4];                \
            float4 b0 = *(const float4*)&Bs[b][kk][tx * 8];                    \
            float4 b1 = *(const float4*)&Bs[b][kk][tx * 8 + 4];                \
            float a[8] = {a0.x, a0.y, a0.z, a0.w, a1.x, a1.y, a1.z, a1.w};     \
            float bv[8] = {b0.x, b0.y, b0.z, b0.w, b1.x, b1.y, b1.z, b1.w};    \
            _Pragma("unroll")                                                  \
            for (int i = 0; i < 8; i++)                                        \
                _Pragma("unroll")                                              \
                for (int j = 0; j < 8; j++)                                    \
                    acc[i][j] = fmaf(a[i], bv[j], acc[i][j]);                  \
        }                                                                      \
    } while (0)

    const int T = K / 16;
    LOAD_REGS(0);
    STORE_SMEM(0);
    __syncthreads();
    int buf = 0;
    for (int t = 1; t < T; t++) {
        LOAD_REGS(t * 16);
        COMPUTE(buf);
        STORE_SMEM(buf ^ 1);
        __syncthreads();
        buf ^= 1;
    }
    COMPUTE(buf);

#undef LOAD_REGS
#undef STORE_SMEM
#undef COMPUTE

    float s = cscale * (scale_ptr ? *scale_ptr : 1.0f);
    if (EPI == 1) {
        float local = 0.0f;
#pragma unroll
        for (int i = 0; i < 8; i++) {
            long row = m0 + ty * 8 + i;
#pragma unroll
            for (int j = 0; j < 8; j++) {
                long idx = row * (long)ldc + n0 + tx * 8 + j;
                float v = s * acc[i][j];
                v = v > 0.0f ? v : 0.0f;
                C[idx] = v;
                local += v * v;
            }
        }
        local = blockRedSum<256>(local);
        if (tid == 0) atomicAdd(&e_ptr[m0 / LL], -0.5f * local);
    } else {
#pragma unroll
        for (int i = 0; i < 8; i++) {
            long row = m0 + ty * 8 + i;
#pragma unroll
            for (int j = 0; j < 8; j++) {
                long idx = row * (long)ldc + n0 + tx * 8 + j;
                float v = s * acc[i][j];
                C[idx] = accum ? (C[idx] + v) : v;
            }
        }
    }
}

// ====== merged per-head attention-gradient GEMM: one launch for both =======
// grid.z in [0, 2*B*H): z < B*H   -> C[:,0:768]   = P   @ K   (A not transposed)
//                       z >= B*H  -> C[:,768:...] = P^T @ Q   (A transposed)
// Tile 128x64, 8x4 microtile, double-buffered. K = LL = 1024.
__global__ __launch_bounds__(256) void gemmAtt(
    const float* __restrict__ Patt, const float* __restrict__ QK, float* __restrict__ Dq)
{
    __shared__ float As[2][16][132];
    __shared__ float Bs[2][16][68];
    int z = blockIdx.z;
    bool trans = z >= BB * HH;
    int bh = trans ? z - BB * HH : z;
    int bo = bh / HH, bi = bh % HH;
    const long sHLL = (long)HH * LL * LL, sLLL = (long)LL * LL;
    const long sL2 = (long)LL * DD2;
    const float* A = Patt + bo * sHLL + bi * sLLL;
    const float* Bm = QK + bo * sL2 + bi * HEADD + (trans ? 0 : DD);  // q : k
    float* C = Dq + bo * sL2 + bi * HEADD + (trans ? DD : 0);
    const int lda = LL, ldb = DD2, ldc = DD2;
    int m0 = blockIdx.y * 128, n0 = 0;       // N = 64 -> single n-block
    int tid = threadIdx.x;
    int tx = tid & 15, ty = tid >> 4;
    int br = tid >> 5, bc = tid & 31;

    float acc[8][4];
#pragma unroll
    for (int i = 0; i < 8; i++)
#pragma unroll
        for (int j = 0; j < 4; j++) acc[i][j] = 0.0f;

    float ra[8];  float4 va0, va1;
    float4 vb;

#define LOAD_REGS(k0)                                                          \
    do {                                                                       \
        if (!trans) {                                                          \
            _Pragma("unroll")                                                  \
            for (int r = 0; r < 8; r++)                                        \
                ra[r] = A[(long)(m0 + ty + 16 * r) * lda + ((k0) + tx)];       \
        } else {                                                               \
            va0 = *(const float4*)(A + (long)((k0) + br) * lda + m0 + bc * 4); \
            va1 = *(const float4*)(A + (long)((k0) + br + 8) * lda + m0 + bc * 4);\
        }                                                                      \
        vb = *(const float4*)(Bm + (long)((k0) + ty) * ldb + n0 + tx * 4);     \
    } while (0)

#define STORE_SMEM(b)                                                          \
    do {                                                                       \
        if (!trans) {                                                          \
            _Pragma("unroll")                                                  \
            for (int r = 0; r < 8; r++) As[b][tx][ty + 16 * r] = ra[r];        \
        } else {                                                               \
            *(float4*)&As[b][br][bc * 4] = va0;                                \
            *(float4*)&As[b][br + 8][bc * 4] = va1;                            \
        }                                                                      \
        *(float4*)&Bs[b][ty][tx * 4] = vb;                                     \
    } while (0)

#define COMPUTE(b)                                                             \
    do {                                                                       \
        _Pragma("unroll")                                                      \
        for (int kk = 0; kk < 16; kk++) {                                      \
            float4 a0 = *(const float4*)&As[b][kk][ty * 8];                    \
            float4 a1 = *(const float4*)&As[b][kk][ty * 8 + 4];                \
            float4 b4 = *(const float4*)&Bs[b][kk][tx * 4];                    \
            float a[8] = {a0.x, a0.y, a0.z, a0.w, a1.x, a1.y, a1.z, a1.w};     \
            float bv[4] = {b4.x, b4.y, b4.z, b4.w};                            \
            _Pragma("unroll")                                                  \
            for (int i = 0; i < 8; i++)                                        \
                _Pragma("unroll")                                              \
                for (int j = 0; j < 4; j++)                                    \
                    acc[i][j] = fmaf(a[i], bv[j], acc[i][j]);                  \
        }                                                                      \
    } while (0)

    const int T = LL / 16;
    LOAD_REGS(0);
    STORE_SMEM(0);
    __syncthreads();
    int buf = 0;
    for (int t = 1; t < T; t++) {
        LOAD_REGS(t * 16);
        COMPUTE(buf);
        STORE_SMEM(buf ^ 1);
        __syncthreads();
        buf ^= 1;
    }
    COMPUTE(buf);

#undef LOAD_REGS
#undef STORE_SMEM
#undef COMPUTE

#pragma unroll
    for (int i = 0; i < 8; i++) {
        long row = m0 + ty * 8 + i;
#pragma unroll
        for (int j = 0; j < 4; j++) {
            C[row * (long)ldc + n0 + tx * 4 + j] = acc[i][j];
        }
    }
}

// ---------------- pointwise / norm / softmax kernels -----------------------
__global__ void init_kernel(const float* __restrict__ xin,
                            const float* __restrict__ pos,
                            float* __restrict__ x)
{
    for (long i = (long)blockIdx.x * blockDim.x + threadIdx.x; i < ND;
         i += (long)gridDim.x * blockDim.x) {
        x[i] = xin[i] + pos[i % ((long)LL * DD)];
    }
}

__global__ void zero_kernel(float* __restrict__ p, int n)
{
    if ((int)threadIdx.x < n) p[threadIdx.x] = 0.0f;
}

__global__ __launch_bounds__(256) void ln_kernel(const float* __restrict__ x,
                                                 const float* __restrict__ w,
                                                 const float* __restrict__ b,
                                                 float* __restrict__ g)
{
    long row = blockIdx.x;
    const float* xr = x + row * DD;
    float* gr = g + row * DD;
    float s = 0.0f, ss = 0.0f;
    for (int d = threadIdx.x; d < DD; d += 256) {
        float v = xr[d];
        s += v;
        ss += v * v;
    }
    s = blockRedSum<256>(s);
    ss = blockRedSum<256>(ss);
    float mu = s * (1.0f / DD);
    float var = ss * (1.0f / DD) - mu * mu;
    float inv = rsqrtf(var + LN_EPS_C);
    for (int d = threadIdx.x; d < DD; d += 256) {
        gr[d] = (xr[d] - mu) * inv * w[d] + b[d];
    }
}

// One block per attention row: att -> P in place, energy += -(1/beta)*lse
__global__ __launch_bounds__(128) void softmax_kernel(float* __restrict__ att,
                                                      const float* __restrict__ beta_attn,
                                                      float* __restrict__ e_slot)
{
    int bh = blockIdx.y;             // 0..B*H-1
    int h = bh % HH;
    int b = bh / HH;
    float beta = beta_attn[h];
    float* row = att + (long)bh * LL * LL + (long)blockIdx.x * LL;
    float v[8];
    float m = -INFINITY;
#pragma unroll
    for (int i = 0; i < 8; i++) {
        v[i] = beta * row[threadIdx.x + i * 128];
        m = fmaxf(m, v[i]);
    }
    m = blockRedMax<128>(m);
    float ssum = 0.0f;
#pragma unroll
    for (int i = 0; i < 8; i++) {
        v[i] = expf(v[i] - m);
        ssum += v[i];
    }
    ssum = blockRedSum<128>(ssum);
    float inv = 1.0f / ssum;
#pragma unroll
    for (int i = 0; i < 8; i++) row[threadIdx.x + i * 128] = v[i] * inv;
    if (threadIdx.x == 0) {
        float lse = m + logf(ssum);
        atomicAdd(&e_slot[b], -(1.0f / beta) * lse);
    }
}

// ---------------- host side -------------------------------------------------
static void launch_gemm128(bool tb,
                           const float* A, const float* B, float* C,
                           int M, int N, int K, int lda, int ldb, int ldc,
                           long sA1, long sA2, long sB1, long sB2, long sC1, long sC2,
                           int nbatch, int inner, const float* scale, float cscale, int accum)
{
    dim3 grid(N / 128, M / 128, nbatch), block(256);
    if (!tb)
        gemm128<false, 0><<<grid, block>>>(A, B, C, M, N, K, lda, ldb, ldc,
                                           sA1, sA2, sB1, sB2, sC1, sC2, inner, scale, cscale, accum, nullptr);
    else
        gemm128<true, 0><<<grid, block>>>(A, B, C, M, N, K, lda, ldb, ldc,
                                          sA1, sA2, sB1, sB2, sC1, sC2, inner, scale, cscale, accum, nullptr);
}

#define SYMADDR(p, s) do { void* _t = nullptr; cudaGetSymbolAddress(&_t, s); (p) = (float*)_t; } while (0)

extern "C" void kernel_launch(void* const* d_in, const int* in_sizes, int n_in,
                              void* d_out, int out_size)
{
    (void)in_sizes; (void)n_in; (void)out_size;
    const float* in_x     = (const float*)d_in[0];  // [B,L,D]
    const float* pos_emb  = (const float*)d_in[1];  // [L,D]
    const float* Wq       = (const float*)d_in[2];  // [H,HEAD,D] == [768,768]
    const float* Wk       = (const float*)d_in[3];  // [768,768]
    const float* beta_att = (const float*)d_in[4];  // [H]
    const float* W_hop    = (const float*)d_in[5];  // [D,HID]
    const float* beta_hop = (const float*)d_in[6];  // [1]
    const float* ln_w     = (const float*)d_in[7];  // [D]
    const float* ln_b     = (const float*)d_in[8];  // [D]

    float* x   = (float*)d_out;     // working x lives in output buffer
    float* eng = x + ND;            // [NITER, B]

    float *pg, *pqk, *pd, *pwc, *php, *patt;
    SYMADDR(pg, g_g);   SYMADDR(pqk, g_qk);  SYMADDR(pd, g_d);
    SYMADDR(pwc, g_wc); SYMADDR(php, g_hp);  SYMADDR(patt, g_att);

    // Build combined weight Wc = [Wq ; Wk]  (1536 x 768), once per launch.
    cudaMemcpyAsync(pwc,                 Wq, (size_t)DD * DD * sizeof(float),
                    cudaMemcpyDeviceToDevice, 0);
    cudaMemcpyAsync(pwc + (long)DD * DD, Wk, (size_t)DD * DD * sizeof(float),
                    cudaMemcpyDeviceToDevice, 0);

    init_kernel<<<2048, 256>>>(in_x, pos_emb, x);
    zero_kernel<<<1, 64>>>(eng, NITER * BB);

    const long sL2 = (long)LL * DD2;     // per-batch stride in qk / d (row 1536)
    const long sHLL = (long)HH * LL * LL;
    const long sLLL = (long)LL * LL;

    for (int it = 0; it < NITER; ++it) {
        float* e_slot = eng + it * BB;

        // g = LN(x)
        ln_kernel<<<BB * LL, 256>>>(x, ln_w, ln_b, pg);

        // qk = g @ Wc^T         [4096,768] x [1536,768]^T -> [4096,1536]
        launch_gemm128(true, pg, pwc, pqk, BB * LL, DD2, DD, DD, DD, DD2,
                       0, 0, 0, 0, 0, 0, 1, 1, nullptr, 1.0f, 0);

        // att[b,h] = Q_bh @ K_bh^T   per (b,h): [1024,64] x [1024,64]^T
        launch_gemm128(true, pqk, pqk + DD, patt, LL, LL, HEADD, DD2, DD2, LL,
                       sL2, HEADD, sL2, HEADD, sHLL, sLLL, BB * HH, HH, nullptr, 1.0f, 0);

        // softmax(beta*att) in place + energy(lse)
        softmax_kernel<<<dim3(LL, BB * HH), 128>>>(patt, beta_att, e_slot);

        // d[:,0:768] = P @ K  and  d[:,768:1536] = P^T @ Q, one merged launch
        {
            dim3 grid(1, LL / 128, 2 * BB * HH), block(256);
            gemmAtt<<<grid, block>>>(patt, pqk, pd);
        }

        // x += alpha * d @ Wc       [4096,1536] x [1536,768]  (fused update)
        launch_gemm128(false, pd, pwc, x, BB * LL, DD, DD2, DD2, DD, DD,
                       0, 0, 0, 0, 0, 0, 1, 1, nullptr, ALPHA_C, 1);

        // r = relu(beta_hop * g @ W_hop) with fused energy epilogue
        {
            dim3 grid(HIDD / 128, (BB * LL) / 128, 1), block(256);
            gemm128<false, 1><<<grid, block>>>(
                pg, W_hop, php, BB * LL, HIDD, DD, DD, HIDD, HIDD,
                0, 0, 0, 0, 0, 0, 1, beta_hop, 1.0f, 0, e_slot);
        }

        // x += alpha * beta_hop * r @ W_hop^T    [4096,3072] x [768,3072]^T
        launch_gemm128(true, php, W_hop, x, BB * LL, DD, HIDD, HIDD, HIDD, DD,
                       0, 0, 0, 0, 0, 0, 1, 1, beta_hop, ALPHA_C, 1);
    }
}

// round 14
// speedup vs baseline: 2.3243x; 2.3243x over previous
#include <cuda_runtime.h>
#include <math.h>
#include <stdint.h>

#define BB 4
#define LL 1024
#define DD 768
#define DD2 1536
#define HH 12
#define HEADD 64
#define HIDD 3072
#define NITER 12
#define ALPHA_C 0.1f
#define LN_EPS_C 1e-5f

#define ND ((long)BB * LL * DD)          /* 3,145,728 */
#define ND2 ((long)BB * LL * DD2)        /* 6,291,456 */
#define NH ((long)BB * LL * HIDD)        /* 12,582,912 */
#define NATT ((long)BB * HH * LL * LL)   /* 50,331,648 */

// ---------------- scratch (__device__ globals; no allocs allowed) ----------
__device__ float g_g[ND];        // layernorm output
__device__ float g_qk[ND2];      // [B*L, 1536]: cols 0:768 = q, 768:1536 = k
__device__ float g_d[ND2];       // [B*L, 1536]: cols 0:768 = P@K, 768:1536 = P^T@Q
__device__ float g_wc[DD2 * DD]; // combined [Wq; Wk]  (1536 x 768)
__device__ float g_hp[NH];       // relu(beta_hop * g @ W_hop)
__device__ float g_att[NATT];    // attention logits -> probabilities in place

// ---------------- tf32 helpers ---------------------------------------------
__device__ __forceinline__ float tf32r(float x) {
    uint32_t u;
    asm("cvt.rna.tf32.f32 %0, %1;" : "=r"(u) : "f"(x));
    return __uint_as_float(u);
}
__device__ __forceinline__ void mma_tf32(float c[4],
                                         uint32_t a0, uint32_t a1, uint32_t a2, uint32_t a3,
                                         uint32_t b0, uint32_t b1) {
    asm volatile(
        "mma.sync.aligned.m16n8k8.row.col.f32.tf32.tf32.f32 "
        "{%0,%1,%2,%3}, {%4,%5,%6,%7}, {%8,%9}, {%0,%1,%2,%3};"
        : "+f"(c[0]), "+f"(c[1]), "+f"(c[2]), "+f"(c[3])
        : "r"(a0), "r"(a1), "r"(a2), "r"(a3), "r"(b0), "r"(b1));
}

// ---------------- reductions ----------------------------------------------
__device__ __forceinline__ float warpRedSum(float v) {
#pragma unroll
    for (int o = 16; o > 0; o >>= 1) v += __shfl_xor_sync(0xffffffffu, v, o);
    return v;
}
__device__ __forceinline__ float warpRedMax(float v) {
#pragma unroll
    for (int o = 16; o > 0; o >>= 1) v = fmaxf(v, __shfl_xor_sync(0xffffffffu, v, o));
    return v;
}
template <int NT>
__device__ __forceinline__ float blockRedSum(float v) {
    __shared__ float sh[NT / 32];
    int lane = threadIdx.x & 31, w = threadIdx.x >> 5;
    v = warpRedSum(v);
    if (lane == 0) sh[w] = v;
    __syncthreads();
    if (w == 0) {
        float t = (lane < NT / 32) ? sh[lane] : 0.0f;
        t = warpRedSum(t);
        if (lane == 0) sh[0] = t;
    }
    __syncthreads();
    float r = sh[0];
    __syncthreads();
    return r;
}
template <int NT>
__device__ __forceinline__ float blockRedMax(float v) {
    __shared__ float sh[NT / 32];
    int lane = threadIdx.x & 31, w = threadIdx.x >> 5;
    v = warpRedMax(v);
    if (lane == 0) sh[w] = v;
    __syncthreads();
    if (w == 0) {
        float t = (lane < NT / 32) ? sh[lane] : -INFINITY;
        t = warpRedMax(t);
        if (lane == 0) sh[0] = t;
    }
    __syncthreads();
    float r = sh[0];
    __syncthreads();
    return r;
}

// =============== 128x128x16 TF32 tensor-core GEMM, double-buffered =========
// A is always [M,K] row-major.
//   TB=false: B is [K,N] row-major.  TB=true: B is [N,K] row-major.
// EPI==1: v = relu(s*acc); C = v; e_ptr[m0/LL] += -0.5*sum v^2 (block-reduced)
// Batched via grid.z: offset = (z/inner)*s?1 + (z%inner)*s?2
// 8 warps: warp tile 64(m) x 32(n); mma.m16n8k8, k-tile 16 (2 k8 steps).
template <bool TB, int EPI>
__global__ __launch_bounds__(256, 2) void gemm128(
    const float* __restrict__ A, const float* __restrict__ Bm, float* __restrict__ C,
    int M, int N, int K, int lda, int ldb, int ldc,
    long sA1, long sA2, long sB1, long sB2, long sC1, long sC2, int inner,
    const float* __restrict__ scale_ptr, float cscale, int accum,
    float* __restrict__ e_ptr)
{
    __shared__ float As[2][16][136];   // [k][m], pad 136 -> frag LDS conflict-free
    __shared__ float Bs[2][16][136];   // [k][n]
    int bz = blockIdx.z;
    int bo = bz / inner, bi = bz % inner;
    A  += bo * sA1 + bi * sA2;
    Bm += bo * sB1 + bi * sB2;
    C  += bo * sC1 + bi * sC2;
    int m0 = blockIdx.y * 128, n0 = blockIdx.x * 128;
    int tid = threadIdx.x;
    int tx = tid & 15, ty = tid >> 4;          // load coords
    int br = tid >> 5, bc = tid & 31;          // B float4-load coords (TB=false)
    int wid = tid >> 5, lane = tid & 31;
    int wm = wid & 1, wn = wid >> 1;           // warp tile: 64m x 32n
    int g8 = lane >> 2, t4 = lane & 3;

    float acc[4][4][4];                        // [m-frag][n-frag][c0..c3]
#pragma unroll
    for (int i = 0; i < 4; i++)
#pragma unroll
        for (int j = 0; j < 4; j++)
#pragma unroll
            for (int r = 0; r < 4; r++) acc[i][j][r] = 0.0f;

    float ra[8];              // A staging: 8 scalars (transposed store)
    float rb[8];              // B staging TB=true: 8 scalars
    float4 vb0, vb1;          // B staging TB=false: 2 float4

#define LOAD_REGS(k0)                                                          \
    do {                                                                       \
        _Pragma("unroll")                                                      \
        for (int r = 0; r < 8; r++)                                            \
            ra[r] = A[(long)(m0 + ty + 16 * r) * lda + ((k0) + tx)];           \
        if (!TB) {                                                             \
            vb0 = *(const float4*)(Bm + (long)((k0) + br) * ldb + n0 + bc * 4);\
            vb1 = *(const float4*)(Bm + (long)((k0) + br + 8) * ldb + n0 + bc * 4);\
        } else {                                                               \
            _Pragma("unroll")                                                  \
            for (int r = 0; r < 8; r++)                                        \
                rb[r] = Bm[(long)(n0 + ty + 16 * r) * ldb + ((k0) + tx)];      \
        }                                                                      \
    } while (0)

#define STORE_SMEM(b)                                                          \
    do {                                                                       \
        _Pragma("unroll")                                                      \
        for (int r = 0; r < 8; r++) As[b][tx][ty + 16 * r] = tf32r(ra[r]);     \
        if (!TB) {                                                             \
            float4 w0 = make_float4(tf32r(vb0.x), tf32r(vb0.y), tf32r(vb0.z), tf32r(vb0.w)); \
            float4 w1 = make_float4(tf32r(vb1.x), tf32r(vb1.y), tf32r(vb1.z), tf32r(vb1.w)); \
            *(float4*)&Bs[b][br][bc * 4] = w0;                                 \
            *(float4*)&Bs[b][br + 8][bc * 4] = w1;                             \
        } else {                                                               \
            _Pragma("unroll")                                                  \
            for (int r = 0; r < 8; r++) Bs[b][tx][ty + 16 * r] = tf32r(rb[r]); \
        }                                                                      \
    } while (0)

#define MMA_STEP(b, kb)                                                        \
    do {                                                                       \
        uint32_t bf[4][2];                                                     \
        _Pragma("unroll")                                                      \
        for (int j = 0; j < 4; j++) {                                          \
            int n = wn * 32 + j * 8 + g8;                                      \
            bf[j][0] = __float_as_uint(Bs[b][(kb) + t4][n]);                   \
            bf[j][1] = __float_as_uint(Bs[b][(kb) + t4 + 4][n]);               \
        }                                                                      \
        _Pragma("unroll")                                                      \
        for (int i = 0; i < 4; i++) {                                          \
            int m = wm * 64 + i * 16 + g8;                                     \
            uint32_t a0 = __float_as_uint(As[b][(kb) + t4][m]);                \
            uint32_t a1 = __float_as_uint(As[b][(kb) + t4][m + 8]);            \
            uint32_t a2 = __float_as_uint(As[b][(kb) + t4 + 4][m]);            \
            uint32_t a3 = __float_as_uint(As[b][(kb) + t4 + 4][m + 8]);        \
            _Pragma("unroll")                                                  \
            for (int j = 0; j < 4; j++)                                        \
                mma_tf32(acc[i][j], a0, a1, a2, a3, bf[j][0], bf[j][1]);       \
        }                                                                      \
    } while (0)

#define COMPUTE(b) do { MMA_STEP(b, 0); MMA_STEP(b, 8); } while (0)

    const int T = K / 16;
    LOAD_REGS(0);
    STORE_SMEM(0);
    __syncthreads();
    int buf = 0;
    for (int t = 1; t < T; t++) {
        LOAD_REGS(t * 16);
        COMPUTE(buf);
        STORE_SMEM(buf ^ 1);
        __syncthreads();
        buf ^= 1;
    }
    COMPUTE(buf);

#undef LOAD_REGS
#undef STORE_SMEM
#undef MMA_STEP
#undef COMPUTE

    float s = cscale * (scale_ptr ? *scale_ptr : 1.0f);
    if (EPI == 1) {
        float local = 0.0f;
#pragma unroll
        for (int i = 0; i < 4; i++) {
#pragma unroll
            for (int j = 0; j < 4; j++) {
                long r = m0 + wm * 64 + i * 16 + g8;
                long c = n0 + wn * 32 + j * 8 + 2 * t4;
                float v0 = fmaxf(s * acc[i][j][0], 0.0f);
                float v1 = fmaxf(s * acc[i][j][1], 0.0f);
                float v2 = fmaxf(s * acc[i][j][2], 0.0f);
                float v3 = fmaxf(s * acc[i][j][3], 0.0f);
                *(float2*)&C[r * (long)ldc + c] = make_float2(v0, v1);
                *(float2*)&C[(r + 8) * (long)ldc + c] = make_float2(v2, v3);
                local += v0 * v0 + v1 * v1 + v2 * v2 + v3 * v3;
            }
        }
        local = blockRedSum<256>(local);
        if (tid == 0) atomicAdd(&e_ptr[m0 / LL], -0.5f * local);
    } else {
#pragma unroll
        for (int i = 0; i < 4; i++) {
#pragma unroll
            for (int j = 0; j < 4; j++) {
                long r = m0 + wm * 64 + i * 16 + g8;
                long c = n0 + wn * 32 + j * 8 + 2 * t4;
                long i0 = r * (long)ldc + c;
                long i1 = (r + 8) * (long)ldc + c;
                if (accum) {
                    float2 o0 = *(float2*)&C[i0];
                    float2 o1 = *(float2*)&C[i1];
                    o0.x += s * acc[i][j][0]; o0.y += s * acc[i][j][1];
                    o1.x += s * acc[i][j][2]; o1.y += s * acc[i][j][3];
                    *(float2*)&C[i0] = o0;
                    *(float2*)&C[i1] = o1;
                } else {
                    *(float2*)&C[i0] = make_float2(s * acc[i][j][0], s * acc[i][j][1]);
                    *(float2*)&C[i1] = make_float2(s * acc[i][j][2], s * acc[i][j][3]);
                }
            }
        }
    }
}

// ====== merged per-head attention-gradient GEMM (TF32 tensor cores) ========
// grid.z in [0, 2*B*H): z < B*H   -> C[:,0:768]   = P   @ K
//                       z >= B*H  -> C[:,768:...] = P^T @ Q
// Tile 128x64; 8 warps: warp tile 32(m) x 32(n). K = LL = 1024.
__global__ __launch_bounds__(256) void gemmAtt(
    const float* __restrict__ Patt, const float* __restrict__ QK, float* __restrict__ Dq)
{
    __shared__ float As[2][16][136];
    __shared__ float Bs[2][16][72];
    int z = blockIdx.z;
    bool trans = z >= BB * HH;
    int bh = trans ? z - BB * HH : z;
    int bo = bh / HH, bi = bh % HH;
    const long sHLL = (long)HH * LL * LL, sLLL = (long)LL * LL;
    const long sL2 = (long)LL * DD2;
    const float* A = Patt + bo * sHLL + bi * sLLL;
    const float* Bm = QK + bo * sL2 + bi * HEADD + (trans ? 0 : DD);  // q : k
    float* C = Dq + bo * sL2 + bi * HEADD + (trans ? DD : 0);
    const int lda = LL, ldb = DD2, ldc = DD2;
    int m0 = blockIdx.y * 128;
    int tid = threadIdx.x;
    int tx = tid & 15, ty = tid >> 4;
    int br = tid >> 5, bc = tid & 31;
    int wid = tid >> 5, lane = tid & 31;
    int wm = wid >> 1, wn = wid & 1;           // warp tile: 32m x 32n
    int g8 = lane >> 2, t4 = lane & 3;

    float acc[2][4][4];
#pragma unroll
    for (int i = 0; i < 2; i++)
#pragma unroll
        for (int j = 0; j < 4; j++)
#pragma unroll
            for (int r = 0; r < 4; r++) acc[i][j][r] = 0.0f;

    float ra[8];  float4 va0, va1;
    float4 vb;

#define LOAD_REGS(k0)                                                          \
    do {                                                                       \
        if (!trans) {                                                          \
            _Pragma("unroll")                                                  \
            for (int r = 0; r < 8; r++)                                        \
                ra[r] = A[(long)(m0 + ty + 16 * r) * lda + ((k0) + tx)];       \
        } else {                                                               \
            va0 = *(const float4*)(A + (long)((k0) + br) * lda + m0 + bc * 4); \
            va1 = *(const float4*)(A + (long)((k0) + br + 8) * lda + m0 + bc * 4);\
        }                                                                      \
        vb = *(const float4*)(Bm + (long)((k0) + ty) * ldb + tx * 4);          \
    } while (0)

#define STORE_SMEM(b)                                                          \
    do {                                                                       \
        if (!trans) {                                                          \
            _Pragma("unroll")                                                  \
            for (int r = 0; r < 8; r++) As[b][tx][ty + 16 * r] = tf32r(ra[r]); \
        } else {                                                               \
            float4 w0 = make_float4(tf32r(va0.x), tf32r(va0.y), tf32r(va0.z), tf32r(va0.w)); \
            float4 w1 = make_float4(tf32r(va1.x), tf32r(va1.y), tf32r(va1.z), tf32r(va1.w)); \
            *(float4*)&As[b][br][bc * 4] = w0;                                 \
            *(float4*)&As[b][br + 8][bc * 4] = w1;                             \
        }                                                                      \
        {                                                                      \
            float4 wv = make_float4(tf32r(vb.x), tf32r(vb.y), tf32r(vb.z), tf32r(vb.w)); \
            *(float4*)&Bs[b][ty][tx * 4] = wv;                                 \
        }                                                                      \
    } while (0)

#define MMA_STEP(b, kb)                                                        \
    do {                                                                       \
        uint32_t bf[4][2];                                                     \
        _Pragma("unroll")                                                      \
        for (int j = 0; j < 4; j++) {                                          \
            int n = wn * 32 + j * 8 + g8;                                      \
            bf[j][0] = __float_as_uint(Bs[b][(kb) + t4][n]);                   \
            bf[j][1] = __float_as_uint(Bs[b][(kb) + t4 + 4][n]);               \
        }                                                                      \
        _Pragma("unroll")                                                      \
        for (int i = 0; i < 2; i++) {                                          \
            int m = wm * 32 + i * 16 + g8;                                     \
            uint32_t a0 = __float_as_uint(As[b][(kb) + t4][m]);                \
            uint32_t a1 = __float_as_uint(As[b][(kb) + t4][m + 8]);            \
            uint32_t a2 = __float_as_uint(As[b][(kb) + t4 + 4][m]);            \
            uint32_t a3 = __float_as_uint(As[b][(kb) + t4 + 4][m + 8]);        \
            _Pragma("unroll")                                                  \
            for (int j = 0; j < 4; j++)                                        \
                mma_tf32(acc[i][j], a0, a1, a2, a3, bf[j][0], bf[j][1]);       \
        }                                                                      \
    } while (0)

#define COMPUTE(b) do { MMA_STEP(b, 0); MMA_STEP(b, 8); } while (0)

    const int T = LL / 16;
    LOAD_REGS(0);
    STORE_SMEM(0);
    __syncthreads();
    int buf = 0;
    for (int t = 1; t < T; t++) {
        LOAD_REGS(t * 16);
        COMPUTE(buf);
        STORE_SMEM(buf ^ 1);
        __syncthreads();
        buf ^= 1;
    }
    COMPUTE(buf);

#undef LOAD_REGS
#undef STORE_SMEM
#undef MMA_STEP
#undef COMPUTE

#pragma unroll
    for (int i = 0; i < 2; i++) {
#pragma unroll
        for (int j = 0; j < 4; j++) {
            long r = m0 + wm * 32 + i * 16 + g8;
            long c = wn * 32 + j * 8 + 2 * t4;
            *(float2*)&C[r * (long)ldc + c] = make_float2(acc[i][j][0], acc[i][j][1]);
            *(float2*)&C[(r + 8) * (long)ldc + c] = make_float2(acc[i][j][2], acc[i][j][3]);
        }
    }
}

// ---------------- pointwise / norm / softmax kernels -----------------------
__global__ void init_kernel(const float* __restrict__ xin,
                            const float* __restrict__ pos,
                            float* __restrict__ x)
{
    for (long i = (long)blockIdx.x * blockDim.x + threadIdx.x; i < ND;
         i += (long)gridDim.x * blockDim.x) {
        x[i] = xin[i] + pos[i % ((long)LL * DD)];
    }
}

__global__ void zero_kernel(float* __restrict__ p, int n)
{
    if ((int)threadIdx.x < n) p[threadIdx.x] = 0.0f;
}

__global__ __launch_bounds__(256) void ln_kernel(const float* __restrict__ x,
                                                 const float* __restrict__ w,
                                                 const float* __restrict__ b,
                                                 float* __restrict__ g)
{
    long row = blockIdx.x;
    const float* xr = x + row * DD;
    float* gr = g + row * DD;
    float s = 0.0f, ss = 0.0f;
    for (int d = threadIdx.x; d < DD; d += 256) {
        float v = xr[d];
        s += v;
        ss += v * v;
    }
    s = blockRedSum<256>(s);
    ss = blockRedSum<256>(ss);
    float mu = s * (1.0f / DD);
    float var = ss * (1.0f / DD) - mu * mu;
    float inv = rsqrtf(var + LN_EPS_C);
    for (int d = threadIdx.x; d < DD; d += 256) {
        gr[d] = (xr[d] - mu) * inv * w[d] + b[d];
    }
}

// One block per attention row: att -> P in place, energy += -(1/beta)*lse
__global__ __launch_bounds__(128) void softmax_kernel(float* __restrict__ att,
                                                      const float* __restrict__ beta_attn,
                                                      float* __restrict__ e_slot)
{
    int bh = blockIdx.y;             // 0..B*H-1
    int h = bh % HH;
    int b = bh / HH;
    float beta = beta_attn[h];
    float* row = att + (long)bh * LL * LL + (long)blockIdx.x * LL;
    float v[8];
    float m = -INFINITY;
#pragma unroll
    for (int i = 0; i < 8; i++) {
        v[i] = beta * row[threadIdx.x + i * 128];
        m = fmaxf(m, v[i]);
    }
    m = blockRedMax<128>(m);
    float ssum = 0.0f;
#pragma unroll
    for (int i = 0; i < 8; i++) {
        v[i] = expf(v[i] - m);
        ssum += v[i];
    }
    ssum = blockRedSum<128>(ssum);
    float inv = 1.0f / ssum;
#pragma unroll
    for (int i = 0; i < 8; i++) row[threadIdx.x + i * 128] = v[i] * inv;
    if (threadIdx.x == 0) {
        float lse = m + logf(ssum);
        atomicAdd(&e_slot[b], -(1.0f / beta) * lse);
    }
}

// ---------------- host side -------------------------------------------------
static void launch_gemm128(bool tb,
                           const float* A, const float* B, float* C,
                           int M, int N, int K, int lda, int ldb, int ldc,
                           long sA1, long sA2, long sB1, long sB2, long sC1, long sC2,
                           int nbatch, int inner, const float* scale, float cscale, int accum)
{
    dim3 grid(N / 128, M / 128, nbatch), block(256);
    if (!tb)
        gemm128<false, 0><<<grid, block>>>(A, B, C, M, N, K, lda, ldb, ldc,
                                           sA1, sA2, sB1, sB2, sC1, sC2, inner, scale, cscale, accum, nullptr);
    else
        gemm128<true, 0><<<grid, block>>>(A, B, C, M, N, K, lda, ldb, ldc,
                                          sA1, sA2, sB1, sB2, sC1, sC2, inner, scale, cscale, accum, nullptr);
}

#define SYMADDR(p, s) do { void* _t = nullptr; cudaGetSymbolAddress(&_t, s); (p) = (float*)_t; } while (0)

extern "C" void kernel_launch(void* const* d_in, const int* in_sizes, int n_in,
                              void* d_out, int out_size)
{
    (void)in_sizes; (void)n_in; (void)out_size;
    const float* in_x     = (const float*)d_in[0];  // [B,L,D]
    const float* pos_emb  = (const float*)d_in[1];  // [L,D]
    const float* Wq       = (const float*)d_in[2];  // [H,HEAD,D] == [768,768]
    const float* Wk       = (const float*)d_in[3];  // [768,768]
    const float* beta_att = (const float*)d_in[4];  // [H]
    const float* W_hop    = (const float*)d_in[5];  // [D,HID]
    const float* beta_hop = (const float*)d_in[6];  // [1]
    const float* ln_w     = (const float*)d_in[7];  // [D]
    const float* ln_b     = (const float*)d_in[8];  // [D]

    float* x   = (float*)d_out;     // working x lives in output buffer
    float* eng = x + ND;            // [NITER, B]

    float *pg, *pqk, *pd, *pwc, *php, *patt;
    SYMADDR(pg, g_g);   SYMADDR(pqk, g_qk);  SYMADDR(pd, g_d);
    SYMADDR(pwc, g_wc); SYMADDR(php, g_hp);  SYMADDR(patt, g_att);

    // Build combined weight Wc = [Wq ; Wk]  (1536 x 768), once per launch.
    cudaMemcpyAsync(pwc,                 Wq, (size_t)DD * DD * sizeof(float),
                    cudaMemcpyDeviceToDevice, 0);
    cudaMemcpyAsync(pwc + (long)DD * DD, Wk, (size_t)DD * DD * sizeof(float),
                    cudaMemcpyDeviceToDevice, 0);

    init_kernel<<<2048, 256>>>(in_x, pos_emb, x);
    zero_kernel<<<1, 64>>>(eng, NITER * BB);

    const long sL2 = (long)LL * DD2;     // per-batch stride in qk / d (row 1536)
    const long sHLL = (long)HH * LL * LL;
    const long sLLL = (long)LL * LL;

    for (int it = 0; it < NITER; ++it) {
        float* e_slot = eng + it * BB;

        // g = LN(x)
        ln_kernel<<<BB * LL, 256>>>(x, ln_w, ln_b, pg);

        // qk = g @ Wc^T         [4096,768] x [1536,768]^T -> [4096,1536]
        launch_gemm128(true, pg, pwc, pqk, BB * LL, DD2, DD, DD, DD, DD2,
                       0, 0, 0, 0, 0, 0, 1, 1, nullptr, 1.0f, 0);

        // att[b,h] = Q_bh @ K_bh^T   per (b,h): [1024,64] x [1024,64]^T
        launch_gemm128(true, pqk, pqk + DD, patt, LL, LL, HEADD, DD2, DD2, LL,
                       sL2, HEADD, sL2, HEADD, sHLL, sLLL, BB * HH, HH, nullptr, 1.0f, 0);

        // softmax(beta*att) in place + energy(lse)
        softmax_kernel<<<dim3(LL, BB * HH), 128>>>(patt, beta_att, e_slot);

        // d[:,0:768] = P @ K  and  d[:,768:1536] = P^T @ Q, one merged launch
        {
            dim3 grid(1, LL / 128, 2 * BB * HH), block(256);
            gemmAtt<<<grid, block>>>(patt, pqk, pd);
        }

        // x += alpha * d @ Wc       [4096,1536] x [1536,768]  (fused update)
        launch_gemm128(false, pd, pwc, x, BB * LL, DD, DD2, DD2, DD, DD,
                       0, 0, 0, 0, 0, 0, 1, 1, nullptr, ALPHA_C, 1);

        // r = relu(beta_hop * g @ W_hop) with fused energy epilogue
        {
            dim3 grid(HIDD / 128, (BB * LL) / 128, 1), block(256);
            gemm128<false, 1><<<grid, block>>>(
                pg, W_hop, php, BB * LL, HIDD, DD, DD, HIDD, HIDD,
                0, 0, 0, 0, 0, 0, 1, beta_hop, 1.0f, 0, e_slot);
        }

        // x += alpha * beta_hop * r @ W_hop^T    [4096,3072] x [768,3072]^T
        launch_gemm128(true, php, W_hop, x, BB * LL, DD, HIDD, HIDD, HIDD, DD,
                       0, 0, 0, 0, 0, 0, 1, 1, beta_hop, ALPHA_C, 1);
    }
}